// round 7
// baseline (speedup 1.0000x reference)
#include <cuda_runtime.h>
#include <math.h>

#define B_      32
#define CIN     2048
#define NPIX    625        // 25*25
#define NANC    9
#define HID     9
#define HID2    10         // padded hid (h=9 is zero pad, enables f32x2/STG.64)
#define NPOS    2048
#define NENT    4096
#define MAXINST 256
#define CGROUPS 8          // grid.y
#define CPG     256        // channels per block
#define CSTG    32         // channels per smem stage (lane = channel)
#define NSTG    (CPG/CSTG)     // 8 stages per block
#define NCHUNK  (CIN/CSTG)     // 64 partial chunks total
#define PLN     729        // 27*27 zero-padded plane
#define NI      4          // instances per warp iteration

typedef unsigned long long ull;

// Scratch (device globals: no allocation allowed)
__device__ float d_part[(size_t)NCHUNK * NENT * HID2];   // 10.5 MB, write-once
__device__ float d_H[NENT * HID2];

// ---- f32x2 helpers (sm_103a packed fp32) ----
__device__ __forceinline__ ull pk2(float lo, float hi) {
    ull r; asm("mov.b64 %0, {%1, %2};" : "=l"(r) : "f"(lo), "f"(hi)); return r;
}
__device__ __forceinline__ void fma2(ull& d, ull a, ull b) {
    asm("fma.rn.f32x2 %0, %1, %2, %3;" : "=l"(d) : "l"(a), "l"(b), "l"(d));
}
__device__ __forceinline__ ull add2(ull a, ull b) {
    ull r; asm("add.rn.f32x2 %0, %1, %2;" : "=l"(r) : "l"(a), "l"(b)); return r;
}

// smem float offsets
#define OFF_SW   (CSTG * PLN)               // 23328
#define OFF_RED  (OFF_SW + 9 * 5 * CSTG * 2)  // 23328 + 2880 = 26208 (8B aligned)
#define OFF_POS  (OFF_RED + 8 * 80 * 2)     // + 1280 = 27488
#define SMEM_FLOATS (OFF_POS + 128 + 128 + 4)
#define SMEM_BYTES  (SMEM_FLOATS * 4)       // ~111 KB

// ---------------- K1: sparse 3x3 conv partials, conflict-free lane=channel layout.
// grid = (32 images, 8 channel-groups of 256); block = 256 threads (8 warps).
__global__ void __launch_bounds__(256) k_conv(
    const float* __restrict__ F,
    const float* __restrict__ Wh,
    const int* __restrict__ posi,
    const int* __restrict__ negi)
{
    extern __shared__ float smem[];
    float*  sF   = smem;                                  // 32 planes of 729
    float2* sW   = (float2*)(smem + OFF_SW);              // [t][h2][c] pairs
    ull*    sRed = (ull*)(smem + OFF_RED);                // per-warp 4 reps x 20
    unsigned short* s_pos = (unsigned short*)(smem + OFF_POS);
    unsigned short* s_ent = s_pos + MAXINST;
    int* s_cnt = (int*)(s_ent + MAXINST);

    const int b    = blockIdx.x;
    const int grp  = blockIdx.y;
    const int tid  = threadIdx.x;
    const int lane = tid & 31;
    const int wid  = tid >> 5;

    if (tid == 0) *s_cnt = 0;
    // zero plane borders once (interiors fully rewritten each stage)
    for (int i = tid; i < CSTG * 104; i += 256) {
        int c = i / 104, j = i % 104, off;
        if (j < 27)      off = j;                          // row 0
        else if (j < 54) off = 26 * 27 + (j - 27);         // row 26
        else { int j2 = j - 54; off = (1 + (j2 >> 1)) * 27 + ((j2 & 1) ? 26 : 0); }
        sF[c * PLN + off] = 0.f;
    }
    __syncthreads();

    // gather entries of image b
    for (int e = tid; e < NENT; e += 256) {
        int flat = (e < NPOS) ? posi[e] : negi[e - NPOS];
        if (flat / (NPIX * NANC) == b) {
            int s = atomicAdd(s_cnt, 1);
            if (s < MAXINST) {
                int rem = flat % (NPIX * NANC);
                int pix = rem / NANC;
                int y = pix / 25, x = pix - y * 25;
                s_pos[s] = (unsigned short)((y << 5) | x);
                s_ent[s] = (unsigned short)e;
            }
        }
    }
    __syncthreads();
    const int ninst = min(*s_cnt, MAXINST);
    if (ninst == 0) return;   // block-uniform

    for (int s = 0; s < NSTG; s++) {
        const int cbase = grp * CPG + s * CSTG;
        __syncthreads();   // previous stage fully consumed
        // stage planes: coalesced LDG, scatter into padded interiors
        const float* gsrc = F + ((size_t)b * CIN + cbase) * NPIX;
        for (int i = tid; i < CSTG * NPIX; i += 256) {
            int c = i / NPIX, rem = i - c * NPIX;
            int r = rem / 25, cl = rem - r * 25;
            sF[c * PLN + (r + 1) * 27 + (cl + 1)] = gsrc[i];
        }
        // stage weights as hid-pair float2 [t][h2][c]
        for (int i = tid; i < 9 * 5 * CSTG; i += 256) {
            int t  = i / (5 * CSTG), rm = i % (5 * CSTG);
            int h2 = rm / CSTG,      c  = rm % CSTG;
            int h0 = 2 * h2;
            float lo = Wh[((size_t)h0 * CIN + cbase + c) * 9 + t];
            float hi = (h0 + 1 < HID) ? Wh[((size_t)(h0 + 1) * CIN + cbase + c) * 9 + t] : 0.f;
            sW[i] = make_float2(lo, hi);
        }
        __syncthreads();

        const float* fpl = sF + lane * PLN;   // lane's plane: stride 729 -> conflict-free
        for (int ib = wid * NI; ib < ninst; ib += 8 * NI) {
            int base[NI];
#pragma unroll
            for (int i = 0; i < NI; i++) {
                int ii = ib + i;
                int p = (ii < ninst) ? (int)s_pos[ii] : 0;
                base[i] = (p >> 5) * 27 + (p & 31);   // top-left tap in padded plane
            }
            ull acc[NI][5];
#pragma unroll
            for (int i = 0; i < NI; i++)
#pragma unroll
                for (int h2 = 0; h2 < 5; h2++) acc[i][h2] = 0ull;

#pragma unroll
            for (int t = 0; t < 9; t++) {
                const int off = (t / 3) * 27 + (t % 3);
                ull p2[NI];
#pragma unroll
                for (int i = 0; i < NI; i++) {
                    float v = fpl[base[i] + off];
                    p2[i] = pk2(v, v);
                }
                const float2* wrow = sW + t * (5 * CSTG) + lane;
#pragma unroll
                for (int h2 = 0; h2 < 5; h2++) {
                    ull w2 = *(const ull*)(wrow + h2 * CSTG);   // LDS.64, conflict-free
#pragma unroll
                    for (int i = 0; i < NI; i++) fma2(acc[i][h2], p2[i], w2);
                }
            }

            // reduce over 32 channels: 3 xor-shuffle levels -> groups of 8
#pragma unroll
            for (int m = 1; m <= 4; m <<= 1)
#pragma unroll
                for (int i = 0; i < NI; i++)
#pragma unroll
                    for (int h2 = 0; h2 < 5; h2++)
                        acc[i][h2] = add2(acc[i][h2],
                                          __shfl_xor_sync(0xffffffffu, acc[i][h2], m));
            // reps (lanes 0,8,16,24) deposit their group partials
            ull* rw = sRed + wid * 80;
            if ((lane & 7) == 0) {
                int rep = lane >> 3;
#pragma unroll
                for (int i = 0; i < NI; i++)
#pragma unroll
                    for (int h2 = 0; h2 < 5; h2++)
                        rw[rep * 20 + i * 5 + h2] = acc[i][h2];
            }
            __syncwarp();
            if (lane < 20) {
                int i  = lane / 5, h2 = lane - 5 * i;
                ull v = add2(add2(rw[lane], rw[20 + lane]),
                             add2(rw[40 + lane], rw[60 + lane]));
                if (ib + i < ninst) {
                    int e = s_ent[ib + i];
                    int chunk = grp * NSTG + s;
                    *(ull*)(d_part + ((size_t)chunk * NENT + e) * HID2 + 2 * h2) = v;
                }
            }
            __syncwarp();
        }
    }
}

// ---------------- K2a: reduce 64 chunk partials (coalesced)
__global__ void k_reduce() {
    int t = blockIdx.x * blockDim.x + threadIdx.x;
    if (t >= NENT * HID2) return;
    float s = 0.f;
#pragma unroll
    for (int c = 0; c < NCHUNK; c++) s += d_part[(size_t)c * NENT * HID2 + t];
    d_H[t] = s;
}

// ---------------- K2b: bias + relu + 1x1 convs + box decode
// out: [0,2048) pos_conf | [2048,4096) neg_conf |
//      [4096,12288) pos_offsets[2048][4] | [12288,20480) proposals[2048][4]
__global__ void k_head(const int* __restrict__ posi, const int* __restrict__ negi,
                       const float* __restrict__ pos_ancs,
                       const float* __restrict__ bh,
                       const float* __restrict__ Wc, const float* __restrict__ bc,
                       const float* __restrict__ Wr, const float* __restrict__ br,
                       float* __restrict__ out)
{
    int e = blockIdx.x * blockDim.x + threadIdx.x;
    if (e >= NENT) return;
    int flat = (e < NPOS) ? posi[e] : negi[e - NPOS];
    int anc = flat % NANC;

    float h[HID];
#pragma unroll
    for (int i = 0; i < HID; i++) h[i] = fmaxf(d_H[e * HID2 + i] + bh[i], 0.f);

    float conf = bc[anc];
#pragma unroll
    for (int i = 0; i < HID; i++) conf = fmaf(Wc[anc * HID + i], h[i], conf);
    out[e] = conf;

    if (e < NPOS) {
        float off[4];
#pragma unroll
        for (int j = 0; j < 4; j++) {
            int r = anc * 4 + j;
            float s = br[r];
#pragma unroll
            for (int i = 0; i < HID; i++) s = fmaf(Wr[r * HID + i], h[i], s);
            off[j] = s;
            out[4096 + e * 4 + j] = s;
        }
        const float* pa = pos_ancs + e * 4;
        float cx = (pa[0] + pa[2]) * 0.5f;
        float cy = (pa[1] + pa[3]) * 0.5f;
        float w  = pa[2] - pa[0];
        float hh = pa[3] - pa[1];
        float ncx = fmaf(off[0], w,  cx);
        float ncy = fmaf(off[1], hh, cy);
        float nw  = w  * expf(off[2]);
        float nh  = hh * expf(off[3]);
        out[12288 + e * 4 + 0] = ncx - nw * 0.5f;
        out[12288 + e * 4 + 1] = ncy - nh * 0.5f;
        out[12288 + e * 4 + 2] = ncx + nw * 0.5f;
        out[12288 + e * 4 + 3] = ncy + nh * 0.5f;
    }
}

extern "C" void kernel_launch(void* const* d_in, const int* in_sizes, int n_in,
                              void* d_out, int out_size) {
    const float* F   = (const float*)d_in[0];
    const int*   pi  = (const int*)  d_in[1];
    const int*   ni  = (const int*)  d_in[2];
    const float* pa  = (const float*)d_in[3];
    const float* Wh  = (const float*)d_in[4];
    const float* bh  = (const float*)d_in[5];
    const float* Wc  = (const float*)d_in[6];
    const float* bc  = (const float*)d_in[7];
    const float* Wr  = (const float*)d_in[8];
    const float* br  = (const float*)d_in[9];
    float* out = (float*)d_out;

    cudaFuncSetAttribute(k_conv, cudaFuncAttributeMaxDynamicSharedMemorySize, SMEM_BYTES);
    dim3 grid(B_, CGROUPS);
    k_conv<<<grid, 256, SMEM_BYTES>>>(F, Wh, pi, ni);
    k_reduce<<<(NENT * HID2 + 255) / 256, 256>>>();
    k_head<<<(NENT + 255) / 256, 256>>>(pi, ni, pa, bh, Wc, bc, Wr, br, out);
}

// round 10
// speedup vs baseline: 1.1982x; 1.1982x over previous
#include <cuda_runtime.h>
#include <math.h>

#define B_      32
#define CIN     2048
#define NPIX    625        // 25*25
#define NANC    9
#define HID     9
#define HID2    10         // padded (h=9 zero) -> 5 f32x2 pairs
#define NPOS    2048
#define NENT    4096
#define MAXINST 256
#define CSTG    16         // channels per smem stage
#define PLN     729        // 27*27 zero-padded plane
#define NPER    5          // instances per thread
#define WIN     160        // instances per sweep window (32 lanes * 5)
#define NGRP    18         // grid.y: 16 blocks x 7 stages + 2 x 8 = 128 stages
#define NCHUNKS (NGRP * 8) // 144 partial chunks (8 warps per block)

typedef unsigned long long ull;

// Scratch (device globals: no allocation allowed)
__device__ float d_part[(size_t)NCHUNKS * NENT * HID2];  // ~23.6 MB, write-once
__device__ float d_H[NENT * HID2];

__device__ __forceinline__ ull pk2(float lo, float hi) {
    ull r; asm("mov.b64 %0, {%1, %2};" : "=l"(r) : "f"(lo), "f"(hi)); return r;
}
__device__ __forceinline__ void fma2(ull& d, ull a, ull b) {
    asm("fma.rn.f32x2 %0, %1, %2, %3;" : "=l"(d) : "l"(a), "l"(b), "l"(d));
}

// dynamic smem layout (bytes)
#define OFF_SW    (CSTG * PLN * 4)            // 46656 (8B aligned)
#define OFF_UB    (OFF_SW + CSTG * 45 * 8)    // 46656 + 5760 = 52416
#define OFF_UE    (OFF_UB + MAXINST * 2)
#define OFF_SB    (OFF_UE + MAXINST * 2)
#define OFF_SE    (OFF_SB + MAXINST * 2)
#define OFF_BCNT  (OFF_SE + MAXINST * 2)      // int[32]
#define OFF_BOFF  (OFF_BCNT + 128)            // int[32]
#define OFF_CNT   (OFF_BOFF + 128)
#define SMEM_BYTES (OFF_CNT + 16)

// ---------------- K1: sparse 3x3 conv partials.
// grid = (32 images, 18 channel-groups); block = 256 threads (8 warps).
// lane = instance (residue-sorted -> near-conflict-free patch LDS),
// warp = 2 channels per stage, NPER=5 instances per thread, f32x2 hid-pairs.
__global__ void __launch_bounds__(256, 3) k_conv(
    const float* __restrict__ F,
    const float* __restrict__ Wh,
    const int* __restrict__ posi,
    const int* __restrict__ negi)
{
    extern __shared__ char smem[];
    float* sF = (float*)smem;                       // 16 planes of 729
    ull*   sW = (ull*)(smem + OFF_SW);              // [k][t][h2] dup-pair weights
    unsigned short* s_ub = (unsigned short*)(smem + OFF_UB);
    unsigned short* s_ue = (unsigned short*)(smem + OFF_UE);
    unsigned short* s_sb = (unsigned short*)(smem + OFF_SB);
    unsigned short* s_se = (unsigned short*)(smem + OFF_SE);
    int* s_bcnt = (int*)(smem + OFF_BCNT);
    int* s_boff = (int*)(smem + OFF_BOFF);
    int* s_cnt  = (int*)(smem + OFF_CNT);

    const int b   = blockIdx.x;
    const int g   = blockIdx.y;
    const int c0  = (g < 16) ? g * 112 : 1792 + (g - 16) * 128;
    const int nst = (g < 16) ? 7 : 8;
    const int tid  = threadIdx.x;
    const int lane = tid & 31;
    const int wid  = tid >> 5;

    if (tid == 0) *s_cnt = 0;
    if (tid < 32) s_bcnt[tid] = 0;
    // zero plane borders once (interiors fully rewritten each stage)
    for (int i = tid; i < CSTG * 104; i += 256) {
        int c = i / 104, j = i % 104, off;
        if (j < 27)      off = j;
        else if (j < 54) off = 26 * 27 + (j - 27);
        else { int j2 = j - 54; off = (1 + (j2 >> 1)) * 27 + ((j2 & 1) ? 26 : 0); }
        sF[c * PLN + off] = 0.f;
    }
    __syncthreads();

    // gather entries of image b (unsorted)
    for (int e = tid; e < NENT; e += 256) {
        int flat = (e < NPOS) ? posi[e] : negi[e - NPOS];
        if (flat / (NPIX * NANC) == b) {
            int s = atomicAdd(s_cnt, 1);
            if (s < MAXINST) {
                int rem = flat % (NPIX * NANC);
                int pix = rem / NANC;
                int y = pix / 25, x = pix - y * 25;
                s_ub[s] = (unsigned short)(y * 27 + x);   // top-left tap in padded plane
                s_ue[s] = (unsigned short)e;
            }
        }
    }
    __syncthreads();
    const int ninst = min(*s_cnt, MAXINST);
    if (ninst == 0) return;   // block-uniform

    // counting sort by (base mod 32): count
    for (int i = tid; i < ninst; i += 256) atomicAdd(&s_bcnt[s_ub[i] & 31], 1);
    __syncthreads();
    if (wid == 0) {   // exclusive scan of 32 counts
        int v = s_bcnt[lane];
#pragma unroll
        for (int d = 1; d < 32; d <<= 1) {
            int t = __shfl_up_sync(0xffffffffu, v, d);
            if (lane >= d) v += t;
        }
        s_boff[lane] = v - s_bcnt[lane];
    }
    __syncthreads();
    for (int i = tid; i < ninst; i += 256) {   // scatter
        int bs = s_ub[i];
        int p = atomicAdd(&s_boff[bs & 31], 1);
        s_sb[p] = (unsigned short)bs;
        s_se[p] = s_ue[i];
    }
    __syncthreads();

    // sweeps of 160 instances (almost always exactly one sweep)
    for (int w0 = 0; w0 < ninst; w0 += WIN) {
        int  ibase[NPER];
        bool ival[NPER];
#pragma unroll
        for (int j = 0; j < NPER; j++) {
            int r = w0 + lane * NPER + j;
            ival[j]  = (r < ninst);
            ibase[j] = ival[j] ? (int)s_sb[r] : lane * 20;   // dummy: in-range, spread banks
        }

        ull acc[NPER][5];
#pragma unroll
        for (int j = 0; j < NPER; j++)
#pragma unroll
            for (int h2 = 0; h2 < 5; h2++) acc[j][h2] = 0ull;

        for (int s = 0; s < nst; s++) {
            const int cbase = c0 + s * CSTG;
            __syncthreads();   // previous stage consumed
            // stage planes: coalesced LDG -> padded interiors (conflict-free STS)
            const float* gsrc = F + ((size_t)b * CIN + cbase) * NPIX;
            for (int i = tid; i < CSTG * NPIX; i += 256) {
                int c = i / NPIX, rem = i - c * NPIX;
                int r = rem / 25, cl = rem - r * 25;
                sF[c * PLN + (r + 1) * 27 + (cl + 1)] = gsrc[i];
            }
            // stage weights: sW[k][t][h2] = {W[2h2][c][t], W[2h2+1][c][t]}
            for (int i = tid; i < CSTG * 45; i += 256) {
                int k = i / 45, rm = i % 45, t = rm / 5, h2 = rm % 5;
                int h0 = 2 * h2;
                float lo = Wh[((size_t)h0 * CIN + cbase + k) * 9 + t];
                float hi = (h0 + 1 < HID) ? Wh[((size_t)(h0 + 1) * CIN + cbase + k) * 9 + t] : 0.f;
                ((float2*)sW)[i] = make_float2(lo, hi);
            }
            __syncthreads();

#pragma unroll
            for (int kk = 0; kk < 2; kk++) {
                const int k = wid * 2 + kk;
                const float* fpl = sF + k * PLN;
                const ull*   wk  = sW + k * 45;
#pragma unroll
                for (int t = 0; t < 9; t++) {
                    const int off = (t / 3) * 27 + (t % 3);
                    ull p2[NPER];
#pragma unroll
                    for (int j = 0; j < NPER; j++) {
                        float v = fpl[ibase[j] + off];
                        p2[j] = pk2(v, v);
                    }
                    ull w2[5];
#pragma unroll
                    for (int h2 = 0; h2 < 5; h2++) w2[h2] = wk[t * 5 + h2];
#pragma unroll
                    for (int j = 0; j < NPER; j++)
#pragma unroll
                        for (int h2 = 0; h2 < 5; h2++)
                            fma2(acc[j][h2], p2[j], w2[h2]);
                }
            }
        }

        // write-once partials: chunk = (g, warp)
        const int chunk = g * 8 + wid;
        float* cp = d_part + (size_t)chunk * NENT * HID2;
#pragma unroll
        for (int j = 0; j < NPER; j++) {
            if (!ival[j]) continue;
            int e = s_se[w0 + lane * NPER + j];
            ull* dst = (ull*)(cp + e * HID2);
#pragma unroll
            for (int h2 = 0; h2 < 5; h2++) dst[h2] = acc[j][h2];
        }
        __syncthreads();   // s_sb/s_se reads done before (rare) next sweep restages
    }
}

// ---------------- K2a: reduce 144 chunk partials (coalesced, L2-resident)
__global__ void k_reduce() {
    int t = blockIdx.x * blockDim.x + threadIdx.x;
    if (t >= NENT * HID2) return;
    float s = 0.f;
#pragma unroll 8
    for (int c = 0; c < NCHUNKS; c++) s += d_part[(size_t)c * NENT * HID2 + t];
    d_H[t] = s;
}

// ---------------- K2b: bias + relu + 1x1 convs + box decode
// out: [0,2048) pos_conf | [2048,4096) neg_conf |
//      [4096,12288) pos_offsets[2048][4] | [12288,20480) proposals[2048][4]
__global__ void k_head(const int* __restrict__ posi, const int* __restrict__ negi,
                       const float* __restrict__ pos_ancs,
                       const float* __restrict__ bh,
                       const float* __restrict__ Wc, const float* __restrict__ bc,
                       const float* __restrict__ Wr, const float* __restrict__ br,
                       float* __restrict__ out)
{
    int e = blockIdx.x * blockDim.x + threadIdx.x;
    if (e >= NENT) return;
    int flat = (e < NPOS) ? posi[e] : negi[e - NPOS];
    int anc = flat % NANC;

    float h[HID];
#pragma unroll
    for (int i = 0; i < HID; i++) h[i] = fmaxf(d_H[e * HID2 + i] + bh[i], 0.f);

    float conf = bc[anc];
#pragma unroll
    for (int i = 0; i < HID; i++) conf = fmaf(Wc[anc * HID + i], h[i], conf);
    out[e] = conf;

    if (e < NPOS) {
        float off[4];
#pragma unroll
        for (int j = 0; j < 4; j++) {
            int r = anc * 4 + j;
            float s = br[r];
#pragma unroll
            for (int i = 0; i < HID; i++) s = fmaf(Wr[r * HID + i], h[i], s);
            off[j] = s;
            out[4096 + e * 4 + j] = s;
        }
        const float* pa = pos_ancs + e * 4;
        float cx = (pa[0] + pa[2]) * 0.5f;
        float cy = (pa[1] + pa[3]) * 0.5f;
        float w  = pa[2] - pa[0];
        float hh = pa[3] - pa[1];
        float ncx = fmaf(off[0], w,  cx);
        float ncy = fmaf(off[1], hh, cy);
        float nw  = w  * expf(off[2]);
        float nh  = hh * expf(off[3]);
        out[12288 + e * 4 + 0] = ncx - nw * 0.5f;
        out[12288 + e * 4 + 1] = ncy - nh * 0.5f;
        out[12288 + e * 4 + 2] = ncx + nw * 0.5f;
        out[12288 + e * 4 + 3] = ncy + nh * 0.5f;
    }
}

extern "C" void kernel_launch(void* const* d_in, const int* in_sizes, int n_in,
                              void* d_out, int out_size) {
    const float* F   = (const float*)d_in[0];
    const int*   pi  = (const int*)  d_in[1];
    const int*   ni  = (const int*)  d_in[2];
    const float* pa  = (const float*)d_in[3];
    const float* Wh  = (const float*)d_in[4];
    const float* bh  = (const float*)d_in[5];
    const float* Wc  = (const float*)d_in[6];
    const float* bc  = (const float*)d_in[7];
    const float* Wr  = (const float*)d_in[8];
    const float* br  = (const float*)d_in[9];
    float* out = (float*)d_out;

    cudaFuncSetAttribute(k_conv, cudaFuncAttributeMaxDynamicSharedMemorySize, SMEM_BYTES);
    dim3 grid(B_, NGRP);
    k_conv<<<grid, 256, SMEM_BYTES>>>(F, Wh, pi, ni);
    k_reduce<<<(NENT * HID2 + 255) / 256, 256>>>();
    k_head<<<(NENT + 255) / 256, 256>>>(pi, ni, pa, bh, Wc, bc, Wr, br, out);
}

// round 11
// speedup vs baseline: 1.6922x; 1.4123x over previous
#include <cuda_runtime.h>
#include <math.h>

#define B_      32
#define CIN     2048
#define NPIX    625        // 25*25
#define NANC    9
#define HID     9
#define HID2    10         // padded (h=9 zero) -> 5 f32x2 pairs
#define NPOS    2048
#define NENT    4096
#define MAXINST 256
#define CSTG    16         // channels per smem stage
#define NPER    5          // instances per thread
#define WIN     160        // instances per sweep (32 lanes * 5)
#define NGRP    18         // grid.y: 16 blocks x 7 stages + 2 x 8 = 128 stages
#define NCHUNKS (NGRP * 8) // 144 partial chunks (8 warps per block)

typedef unsigned long long ull;

// Scratch (device globals: no allocation allowed)
__device__ float d_part[(size_t)NCHUNKS * NENT * HID2];  // ~23.6 MB, write-once
__device__ float d_H[NENT * HID2];

__device__ __forceinline__ ull pk2(float lo, float hi) {
    ull r; asm("mov.b64 %0, {%1, %2};" : "=l"(r) : "f"(lo), "f"(hi)); return r;
}
__device__ __forceinline__ void fma2(ull& d, ull a, ull b) {
    asm("fma.rn.f32x2 %0, %1, %2, %3;" : "=l"(d) : "l"(a), "l"(b), "l"(d));
}

// dynamic smem layout (bytes)
#define FBUF      40000                     // 16 * 625 * 4
#define OFF_SW    (2 * FBUF)                // 80000
#define WBUF      5760                      // 16 * 45 * 8
#define OFF_UB    (OFF_SW + 2 * WBUF)       // 91520
#define OFF_UE    (OFF_UB + MAXINST * 2)
#define OFF_SB    (OFF_UE + MAXINST * 2)
#define OFF_SE    (OFF_SB + MAXINST * 2)
#define OFF_BCNT  (OFF_SE + MAXINST * 2)    // int[32]
#define OFF_BOFF  (OFF_BCNT + 128)          // int[32]
#define OFF_CNT   (OFF_BOFF + 128)
#define SMEM_BYTES (OFF_CNT + 16)           // ~93.8 KB -> 2 blocks/SM

// ---------------- K1: sparse 3x3 conv partials.
// grid = (32 images, 18 channel-groups); block = 256 threads (8 warps).
// Unpadded planes (pure-copy staging), double-buffered, 1 barrier/stage.
// lane = instance (residue-sorted), warp = 2 channels/stage, f32x2 hid-pairs,
// border taps via precomputed mask -> predicated LDS.
__global__ void __launch_bounds__(256, 2) k_conv(
    const float* __restrict__ F,
    const float* __restrict__ Wh,
    const int* __restrict__ posi,
    const int* __restrict__ negi)
{
    extern __shared__ char smem[];
    float* sF = (float*)smem;                        // 2 x 16 planes of 625
    ull*   sW = (ull*)(smem + OFF_SW);               // 2 x [k][t][h2] weight pairs
    unsigned short* s_ub = (unsigned short*)(smem + OFF_UB);
    unsigned short* s_ue = (unsigned short*)(smem + OFF_UE);
    unsigned short* s_sb = (unsigned short*)(smem + OFF_SB);
    unsigned short* s_se = (unsigned short*)(smem + OFF_SE);
    int* s_bcnt = (int*)(smem + OFF_BCNT);
    int* s_boff = (int*)(smem + OFF_BOFF);
    int* s_cnt  = (int*)(smem + OFF_CNT);

    const int b    = blockIdx.x;
    const int g    = blockIdx.y;
    const int c0   = (g < 16) ? g * 112 : 1792 + (g - 16) * 128;
    const int nst  = (g < 16) ? 7 : 8;
    const int tid  = threadIdx.x;
    const int lane = tid & 31;
    const int wid  = tid >> 5;

    if (tid == 0) *s_cnt = 0;
    if (tid < 32) s_bcnt[tid] = 0;
    __syncthreads();

    // gather entries of image b; key = conv base offset (y-1)*25+(x-1), stored +64
    for (int e = tid; e < NENT; e += 256) {
        int flat = (e < NPOS) ? posi[e] : negi[e - NPOS];
        if (flat / (NPIX * NANC) == b) {
            int s = atomicAdd(s_cnt, 1);
            if (s < MAXINST) {
                int rem = flat % (NPIX * NANC);
                int pix = rem / NANC;
                int y = pix / 25, x = pix - y * 25;
                s_ub[s] = (unsigned short)((y - 1) * 25 + (x - 1) + 64);
                s_ue[s] = (unsigned short)e;
            }
        }
    }
    __syncthreads();
    const int ninst = min(*s_cnt, MAXINST);
    if (ninst == 0) return;   // block-uniform

    // counting sort by (base mod 32)
    for (int i = tid; i < ninst; i += 256) atomicAdd(&s_bcnt[s_ub[i] & 31], 1);
    __syncthreads();
    if (wid == 0) {
        int v = s_bcnt[lane];
#pragma unroll
        for (int d = 1; d < 32; d <<= 1) {
            int t = __shfl_up_sync(0xffffffffu, v, d);
            if (lane >= d) v += t;
        }
        s_boff[lane] = v - s_bcnt[lane];
    }
    __syncthreads();
    for (int i = tid; i < ninst; i += 256) {
        int bs = s_ub[i];
        int p = atomicAdd(&s_boff[bs & 31], 1);
        s_sb[p] = (unsigned short)bs;
        s_se[p] = s_ue[i];
    }
    __syncthreads();

    float4 rf[10];     // staged F for one 16-channel stage (pure linear copy)
    float2 wreg[3];    // staged weights

    for (int w0 = 0; w0 < ninst; w0 += WIN) {
        // per-thread instances: base + 9-bit border mask
        int      ibase[NPER];
        unsigned mk[NPER];
        bool     ival[NPER];
#pragma unroll
        for (int j = 0; j < NPER; j++) {
            int r = w0 + lane * NPER + j;
            ival[j] = (r < ninst);
            if (ival[j]) {
                int base = (int)s_sb[r] - 64;
                ibase[j] = base;
                int v = base + 26;          // = 25*y + x
                int y = v / 25, x = v - 25 * y;
                unsigned m = 0;
#pragma unroll
                for (int t = 0; t < 9; t++) {
                    int dy = t / 3, dx = t - dy * 3;
                    if ((unsigned)(y - 1 + dy) < 25u && (unsigned)(x - 1 + dx) < 25u)
                        m |= 1u << t;
                }
                mk[j] = m;
            } else { ibase[j] = 0; mk[j] = 0u; }
        }

        ull acc[NPER][5];
#pragma unroll
        for (int j = 0; j < NPER; j++)
#pragma unroll
            for (int h2 = 0; h2 < 5; h2++) acc[j][h2] = 0ull;

        // prologue: load stage 0 into regs
        {
            const float4* g4 = (const float4*)(F + ((size_t)b * CIN + c0) * NPIX);
#pragma unroll
            for (int it = 0; it < 10; it++) {
                int i4 = it * 256 + tid;
                if (i4 < CSTG * NPIX / 4) rf[it] = g4[i4];
            }
#pragma unroll
            for (int it = 0; it < 3; it++) {
                int i = it * 256 + tid;
                if (i < CSTG * 45) {
                    int k = i / 45, rm = i % 45, t = rm / 5, h2 = rm % 5;
                    int h0 = 2 * h2;
                    float lo = Wh[((size_t)h0 * CIN + c0 + k) * 9 + t];
                    float hi = (h0 + 1 < HID) ? Wh[((size_t)(h0 + 1) * CIN + c0 + k) * 9 + t] : 0.f;
                    wreg[it] = make_float2(lo, hi);
                }
            }
        }

        for (int s = 0; s < nst; s++) {
            const int buf = s & 1;
            // STS staged regs (pure copy, conflict-free)
            float4* s4 = (float4*)(sF + buf * (FBUF / 4));
#pragma unroll
            for (int it = 0; it < 10; it++) {
                int i4 = it * 256 + tid;
                if (i4 < CSTG * NPIX / 4) s4[i4] = rf[it];
            }
            float2* w2d = (float2*)((char*)sW + buf * WBUF);
#pragma unroll
            for (int it = 0; it < 3; it++) {
                int i = it * 256 + tid;
                if (i < CSTG * 45) w2d[i] = wreg[it];
            }
            // prefetch next stage into regs (WAR after STS issue; hides DRAM latency)
            if (s + 1 < nst) {
                const int cb = c0 + (s + 1) * CSTG;
                const float4* g4 = (const float4*)(F + ((size_t)b * CIN + cb) * NPIX);
#pragma unroll
                for (int it = 0; it < 10; it++) {
                    int i4 = it * 256 + tid;
                    if (i4 < CSTG * NPIX / 4) rf[it] = g4[i4];
                }
#pragma unroll
                for (int it = 0; it < 3; it++) {
                    int i = it * 256 + tid;
                    if (i < CSTG * 45) {
                        int k = i / 45, rm = i % 45, t = rm / 5, h2 = rm % 5;
                        int h0 = 2 * h2;
                        float lo = Wh[((size_t)h0 * CIN + cb + k) * 9 + t];
                        float hi = (h0 + 1 < HID) ? Wh[((size_t)(h0 + 1) * CIN + cb + k) * 9 + t] : 0.f;
                        wreg[it] = make_float2(lo, hi);
                    }
                }
            }
            __syncthreads();   // single barrier per stage

            const float* sFb = sF + buf * (FBUF / 4);
            const ull*   sWb = (const ull*)((const char*)sW + buf * WBUF);
#pragma unroll
            for (int kk = 0; kk < 2; kk++) {
                const int k = wid * 2 + kk;
                const float* fpl = sFb + k * NPIX;
                const ull*   wk  = sWb + k * 45;
#pragma unroll
                for (int t = 0; t < 9; t++) {
                    const int off = (t / 3) * 25 + (t % 3);
                    ull w2v[5];
#pragma unroll
                    for (int h2 = 0; h2 < 5; h2++) w2v[h2] = wk[t * 5 + h2];
#pragma unroll
                    for (int j = 0; j < NPER; j++) {
                        float v = 0.f;
                        if (mk[j] >> t & 1u) v = fpl[ibase[j] + off];   // @p LDS
                        ull p2 = pk2(v, v);
#pragma unroll
                        for (int h2 = 0; h2 < 5; h2++) fma2(acc[j][h2], p2, w2v[h2]);
                    }
                }
            }
        }

        // write-once partials: chunk = (g, warp)
        const int chunk = g * 8 + wid;
        float* cp = d_part + (size_t)chunk * NENT * HID2;
#pragma unroll
        for (int j = 0; j < NPER; j++) {
            if (!ival[j]) continue;
            int e = s_se[w0 + lane * NPER + j];
            ull* dst = (ull*)(cp + e * HID2);
#pragma unroll
            for (int h2 = 0; h2 < 5; h2++) dst[h2] = acc[j][h2];
        }
        __syncthreads();   // (rare multi-sweep) buf0 free before next sweep's STS
    }
}

// ---------------- K2a: reduce 144 chunk partials (coalesced, L2-resident)
__global__ void k_reduce() {
    int t = blockIdx.x * blockDim.x + threadIdx.x;
    if (t >= NENT * HID2) return;
    float s = 0.f;
#pragma unroll 8
    for (int c = 0; c < NCHUNKS; c++) s += d_part[(size_t)c * NENT * HID2 + t];
    d_H[t] = s;
}

// ---------------- K2b: bias + relu + 1x1 convs + box decode
// out: [0,2048) pos_conf | [2048,4096) neg_conf |
//      [4096,12288) pos_offsets[2048][4] | [12288,20480) proposals[2048][4]
__global__ void k_head(const int* __restrict__ posi, const int* __restrict__ negi,
                       const float* __restrict__ pos_ancs,
                       const float* __restrict__ bh,
                       const float* __restrict__ Wc, const float* __restrict__ bc,
                       const float* __restrict__ Wr, const float* __restrict__ br,
                       float* __restrict__ out)
{
    int e = blockIdx.x * blockDim.x + threadIdx.x;
    if (e >= NENT) return;
    int flat = (e < NPOS) ? posi[e] : negi[e - NPOS];
    int anc = flat % NANC;

    float h[HID];
#pragma unroll
    for (int i = 0; i < HID; i++) h[i] = fmaxf(d_H[e * HID2 + i] + bh[i], 0.f);

    float conf = bc[anc];
#pragma unroll
    for (int i = 0; i < HID; i++) conf = fmaf(Wc[anc * HID + i], h[i], conf);
    out[e] = conf;

    if (e < NPOS) {
        float off[4];
#pragma unroll
        for (int j = 0; j < 4; j++) {
            int r = anc * 4 + j;
            float s = br[r];
#pragma unroll
            for (int i = 0; i < HID; i++) s = fmaf(Wr[r * HID + i], h[i], s);
            off[j] = s;
            out[4096 + e * 4 + j] = s;
        }
        const float* pa = pos_ancs + e * 4;
        float cx = (pa[0] + pa[2]) * 0.5f;
        float cy = (pa[1] + pa[3]) * 0.5f;
        float w  = pa[2] - pa[0];
        float hh = pa[3] - pa[1];
        float ncx = fmaf(off[0], w,  cx);
        float ncy = fmaf(off[1], hh, cy);
        float nw  = w  * expf(off[2]);
        float nh  = hh * expf(off[3]);
        out[12288 + e * 4 + 0] = ncx - nw * 0.5f;
        out[12288 + e * 4 + 1] = ncy - nh * 0.5f;
        out[12288 + e * 4 + 2] = ncx + nw * 0.5f;
        out[12288 + e * 4 + 3] = ncy + nh * 0.5f;
    }
}

extern "C" void kernel_launch(void* const* d_in, const int* in_sizes, int n_in,
                              void* d_out, int out_size) {
    const float* F   = (const float*)d_in[0];
    const int*   pi  = (const int*)  d_in[1];
    const int*   ni  = (const int*)  d_in[2];
    const float* pa  = (const float*)d_in[3];
    const float* Wh  = (const float*)d_in[4];
    const float* bh  = (const float*)d_in[5];
    const float* Wc  = (const float*)d_in[6];
    const float* bc  = (const float*)d_in[7];
    const float* Wr  = (const float*)d_in[8];
    const float* br  = (const float*)d_in[9];
    float* out = (float*)d_out;

    cudaFuncSetAttribute(k_conv, cudaFuncAttributeMaxDynamicSharedMemorySize, SMEM_BYTES);
    dim3 grid(B_, NGRP);
    k_conv<<<grid, 256, SMEM_BYTES>>>(F, Wh, pi, ni);
    k_reduce<<<(NENT * HID2 + 255) / 256, 256>>>();
    k_head<<<(NENT + 255) / 256, 256>>>(pi, ni, pa, bh, Wc, bc, Wr, br, out);
}

// round 13
// speedup vs baseline: 1.7240x; 1.0188x over previous
#include <cuda_runtime.h>
#include <math.h>

#define B_      32
#define CIN     2048
#define NPIX    625        // 25*25
#define NANC    9
#define HID     9
#define HID2    10         // padded (h=9 zero) -> 5 f32x2 pairs
#define NPOS    2048
#define NENT    4096
#define MAXINST 256
#define CSTG    16         // channels per smem stage (2 per warp)
#define NPER    5          // instances per thread
#define WIN     160        // instances per sweep (32 lanes * 5)
#define NGRP    9          // grid.y -> 288 blocks = single wave at 2/SM
#define NCHUNKS (NGRP * 8) // 72 partial chunks

typedef unsigned long long ull;

// Scratch (device globals: no allocation allowed)
__device__ float d_part[(size_t)NCHUNKS * NENT * HID2];  // ~11.8 MB, write-once
__device__ float d_H[NENT * HID2];
__device__ ull   d_Wp[CIN * 50];   // [c][h2][10 taps] f32x2 pairs (tap 9 = pad)

__device__ __forceinline__ ull pk2(float lo, float hi) {
    ull r; asm("mov.b64 %0, {%1, %2};" : "=l"(r) : "f"(lo), "f"(hi)); return r;
}
__device__ __forceinline__ void fma2(ull& d, ull a, ull b) {
    asm("fma.rn.f32x2 %0, %1, %2, %3;" : "=l"(d) : "l"(a), "l"(b), "l"(d));
}
__device__ __forceinline__ void cpa16(unsigned s, const void* g) {
    asm volatile("cp.async.cg.shared.global [%0], [%1], 16;" :: "r"(s), "l"(g));
}
#define CPA_COMMIT() asm volatile("cp.async.commit_group;")
#define CPA_WAIT0()  asm volatile("cp.async.wait_group 0;" ::: "memory")

// dynamic smem layout (bytes)
#define FBUF      40000                     // 16 * 625 * 4
#define WBUF      6400                      // 16 * 50 * 8
#define OFF_SW    (2 * FBUF)                // 80000
#define OFF_UB    (OFF_SW + 2 * WBUF)       // 92800
#define OFF_UE    (OFF_UB + MAXINST * 2)
#define OFF_SB    (OFF_UE + MAXINST * 2)
#define OFF_SE    (OFF_SB + MAXINST * 2)
#define OFF_BCNT  (OFF_SE + MAXINST * 2)
#define OFF_BOFF  (OFF_BCNT + 128)
#define OFF_CNT   (OFF_BOFF + 128)
#define SMEM_BYTES (OFF_CNT + 16)           // ~94.2 KB -> 2 blocks/SM

// ---------------- K0: pack weights [h][c][3][3] -> [c][h2][10] f32x2 pairs
__global__ void k_prep(const float* __restrict__ Wh) {
    int idx = blockIdx.x * blockDim.x + threadIdx.x;
    if (idx >= CIN * 50) return;
    int c = idx / 50, rm = idx % 50, h2 = rm / 10, t = rm % 10;
    float lo = 0.f, hi = 0.f;
    if (t < 9) {
        lo = Wh[((size_t)(2 * h2) * CIN + c) * 9 + t];
        if (2 * h2 + 1 < HID) hi = Wh[((size_t)(2 * h2 + 1) * CIN + c) * 9 + t];
    }
    ((float2*)d_Wp)[idx] = make_float2(lo, hi);
}

// ---------------- K1: sparse 3x3 conv partials.
// grid = (32 images, 9 channel-groups); block = 256 threads (8 warps).
// cp.async double-buffered staging, 1 barrier/stage, lane=instance
// (residue-sorted), warp = 2 channels/stage, f32x2 hid-pairs, tap-paired
// LDS.128 weight loads, predicated border LDS.
__global__ void __launch_bounds__(256, 2) k_conv(
    const float* __restrict__ F,
    const int* __restrict__ posi,
    const int* __restrict__ negi)
{
    extern __shared__ char smem[];
    float* sF = (float*)smem;                        // 2 x 16 planes of 625
    unsigned short* s_ub = (unsigned short*)(smem + OFF_UB);
    unsigned short* s_ue = (unsigned short*)(smem + OFF_UE);
    unsigned short* s_sb = (unsigned short*)(smem + OFF_SB);
    unsigned short* s_se = (unsigned short*)(smem + OFF_SE);
    int* s_bcnt = (int*)(smem + OFF_BCNT);
    int* s_boff = (int*)(smem + OFF_BOFF);
    int* s_cnt  = (int*)(smem + OFF_CNT);
    const unsigned sm0 = (unsigned)__cvta_generic_to_shared(smem);

    const int b    = blockIdx.x;
    const int g    = blockIdx.y;
    const int c0   = (g < 2) ? g * 240 : 480 + (g - 2) * 224;   // stage-count split
    const int nst  = (g < 2) ? 15 : 14;                          // 2*15+7*14=128
    const int tid  = threadIdx.x;
    const int lane = tid & 31;
    const int wid  = tid >> 5;

    if (tid == 0) *s_cnt = 0;
    if (tid < 32) s_bcnt[tid] = 0;
    __syncthreads();

    // gather entries of image b; key = conv base offset (y-1)*25+(x-1), stored +64
    for (int e = tid; e < NENT; e += 256) {
        int flat = (e < NPOS) ? posi[e] : negi[e - NPOS];
        if (flat / (NPIX * NANC) == b) {
            int s = atomicAdd(s_cnt, 1);
            if (s < MAXINST) {
                int rem = flat % (NPIX * NANC);
                int pix = rem / NANC;
                int y = pix / 25, x = pix - y * 25;
                s_ub[s] = (unsigned short)((y - 1) * 25 + (x - 1) + 64);
                s_ue[s] = (unsigned short)e;
            }
        }
    }
    __syncthreads();
    const int ninst = min(*s_cnt, MAXINST);
    if (ninst == 0) return;   // block-uniform; no cp.async issued yet

    // counting sort by (base mod 32) -> near-conflict-free patch LDS
    for (int i = tid; i < ninst; i += 256) atomicAdd(&s_bcnt[s_ub[i] & 31], 1);
    __syncthreads();
    if (wid == 0) {
        int v = s_bcnt[lane];
#pragma unroll
        for (int d = 1; d < 32; d <<= 1) {
            int t = __shfl_up_sync(0xffffffffu, v, d);
            if (lane >= d) v += t;
        }
        s_boff[lane] = v - s_bcnt[lane];
    }
    __syncthreads();
    for (int i = tid; i < ninst; i += 256) {
        int bs = s_ub[i];
        int p = atomicAdd(&s_boff[bs & 31], 1);
        s_sb[p] = (unsigned short)bs;
        s_se[p] = s_ue[i];
    }
    __syncthreads();

    for (int w0 = 0; w0 < ninst; w0 += WIN) {
        // per-thread instances: base + 9-bit border mask
        int      ibase[NPER];
        unsigned mk[NPER];
        bool     ival[NPER];
#pragma unroll
        for (int j = 0; j < NPER; j++) {
            int r = w0 + lane * NPER + j;
            ival[j] = (r < ninst);
            if (ival[j]) {
                int base = (int)s_sb[r] - 64;
                ibase[j] = base;
                int v = base + 26;          // = 25*y + x
                int y = v / 25, x = v - 25 * y;
                unsigned m = 0;
#pragma unroll
                for (int t = 0; t < 9; t++) {
                    int dy = t / 3, dx = t - dy * 3;
                    if ((unsigned)(y - 1 + dy) < 25u && (unsigned)(x - 1 + dx) < 25u)
                        m |= 1u << t;
                }
                mk[j] = m;
            } else { ibase[j] = 0; mk[j] = 0u; }
        }

        ull acc[NPER][5];
#pragma unroll
        for (int j = 0; j < NPER; j++)
#pragma unroll
            for (int h2 = 0; h2 < 5; h2++) acc[j][h2] = 0ull;

        // cp.async stage issue: F (2500 x 16B) + packed W (400 x 16B)
        auto stage_issue = [&](int s) {
            const int cb = c0 + s * CSTG;
            const char* gF = (const char*)(F + ((size_t)b * CIN + cb) * NPIX);
            const unsigned dF = sm0 + (s & 1) * FBUF;
            for (int i = tid; i < FBUF / 16; i += 256) cpa16(dF + i * 16, gF + i * 16);
            const char* gW = (const char*)(d_Wp + (size_t)cb * 50);
            const unsigned dW = sm0 + OFF_SW + (s & 1) * WBUF;
            for (int i = tid; i < WBUF / 16; i += 256) cpa16(dW + i * 16, gW + i * 16);
            CPA_COMMIT();
        };

        stage_issue(0);
        for (int s = 0; s < nst; s++) {
            CPA_WAIT0();          // this stage's copies (this thread) done
            __syncthreads();      // all threads' copies visible; prev compute done
            if (s + 1 < nst) stage_issue(s + 1);   // overlaps compute below

            const int buf = s & 1;
            const float* sFb = sF + buf * (FBUF / 4);
            const ull*   sWb = (const ull*)(smem + OFF_SW + buf * WBUF);
#pragma unroll
            for (int kk = 0; kk < 2; kk++) {
                const int k = wid * 2 + kk;
                const float* fpl = sFb + k * NPIX;
                const ull*   wk  = sWb + k * 50;
                // tap pairs (0,1)(2,3)(4,5)(6,7): LDS.128 weight loads
#pragma unroll
                for (int tp = 0; tp < 4; tp++) {
                    const int t0 = 2 * tp, t1 = t0 + 1;
                    const int o0 = (t0 / 3) * 25 + t0 % 3;
                    const int o1 = (t1 / 3) * 25 + t1 % 3;
                    ulonglong2 w01[5];
#pragma unroll
                    for (int h2 = 0; h2 < 5; h2++)
                        w01[h2] = *(const ulonglong2*)(wk + h2 * 10 + t0);
#pragma unroll
                    for (int j = 0; j < NPER; j++) {
                        float v0 = 0.f, v1 = 0.f;
                        if (mk[j] >> t0 & 1u) v0 = fpl[ibase[j] + o0];
                        if (mk[j] >> t1 & 1u) v1 = fpl[ibase[j] + o1];
                        ull p0 = pk2(v0, v0), p1 = pk2(v1, v1);
#pragma unroll
                        for (int h2 = 0; h2 < 5; h2++) {
                            fma2(acc[j][h2], p0, w01[h2].x);
                            fma2(acc[j][h2], p1, w01[h2].y);
                        }
                    }
                }
                // tap 8
                {
                    ull w8[5];
#pragma unroll
                    for (int h2 = 0; h2 < 5; h2++) w8[h2] = wk[h2 * 10 + 8];
#pragma unroll
                    for (int j = 0; j < NPER; j++) {
                        float v = 0.f;
                        if (mk[j] >> 8 & 1u) v = fpl[ibase[j] + 52];
                        ull p = pk2(v, v);
#pragma unroll
                        for (int h2 = 0; h2 < 5; h2++) fma2(acc[j][h2], p, w8[h2]);
                    }
                }
            }
        }

        // write-once partials: chunk = (g, warp)
        const int chunk = g * 8 + wid;
        float* cp = d_part + (size_t)chunk * NENT * HID2;
#pragma unroll
        for (int j = 0; j < NPER; j++) {
            if (!ival[j]) continue;
            int e = s_se[w0 + lane * NPER + j];
            ull* dst = (ull*)(cp + e * HID2);
#pragma unroll
            for (int h2 = 0; h2 < 5; h2++) dst[h2] = acc[j][h2];
        }
        __syncthreads();   // (rare multi-sweep) buffers free before restage
    }
}

// ---------------- K2a: reduce 72 chunk partials (coalesced, L2-resident)
__global__ void k_reduce() {
    int t = blockIdx.x * blockDim.x + threadIdx.x;
    if (t >= NENT * HID2) return;
    float s = 0.f;
#pragma unroll 8
    for (int c = 0; c < NCHUNKS; c++) s += d_part[(size_t)c * NENT * HID2 + t];
    d_H[t] = s;
}

// ---------------- K2b: bias + relu + 1x1 convs + box decode
// out: [0,2048) pos_conf | [2048,4096) neg_conf |
//      [4096,12288) pos_offsets[2048][4] | [12288,20480) proposals[2048][4]
__global__ void k_head(const int* __restrict__ posi, const int* __restrict__ negi,
                       const float* __restrict__ pos_ancs,
                       const float* __restrict__ bh,
                       const float* __restrict__ Wc, const float* __restrict__ bc,
                       const float* __restrict__ Wr, const float* __restrict__ br,
                       float* __restrict__ out)
{
    int e = blockIdx.x * blockDim.x + threadIdx.x;
    if (e >= NENT) return;
    int flat = (e < NPOS) ? posi[e] : negi[e - NPOS];
    int anc = flat % NANC;

    float h[HID];
#pragma unroll
    for (int i = 0; i < HID; i++) h[i] = fmaxf(d_H[e * HID2 + i] + bh[i], 0.f);

    float conf = bc[anc];
#pragma unroll
    for (int i = 0; i < HID; i++) conf = fmaf(Wc[anc * HID + i], h[i], conf);
    out[e] = conf;

    if (e < NPOS) {
        float off[4];
#pragma unroll
        for (int j = 0; j < 4; j++) {
            int r = anc * 4 + j;
            float s = br[r];
#pragma unroll
            for (int i = 0; i < HID; i++) s = fmaf(Wr[r * HID + i], h[i], s);
            off[j] = s;
            out[4096 + e * 4 + j] = s;
        }
        const float* pa = pos_ancs + e * 4;
        float cx = (pa[0] + pa[2]) * 0.5f;
        float cy = (pa[1] + pa[3]) * 0.5f;
        float w  = pa[2] - pa[0];
        float hh = pa[3] - pa[1];
        float ncx = fmaf(off[0], w,  cx);
        float ncy = fmaf(off[1], hh, cy);
        float nw  = w  * expf(off[2]);
        float nh  = hh * expf(off[3]);
        out[12288 + e * 4 + 0] = ncx - nw * 0.5f;
        out[12288 + e * 4 + 1] = ncy - nh * 0.5f;
        out[12288 + e * 4 + 2] = ncx + nw * 0.5f;
        out[12288 + e * 4 + 3] = ncy + nh * 0.5f;
    }
}

extern "C" void kernel_launch(void* const* d_in, const int* in_sizes, int n_in,
                              void* d_out, int out_size) {
    const float* F   = (const float*)d_in[0];
    const int*   pi  = (const int*)  d_in[1];
    const int*   ni  = (const int*)  d_in[2];
    const float* pa  = (const float*)d_in[3];
    const float* Wh  = (const float*)d_in[4];
    const float* bh  = (const float*)d_in[5];
    const float* Wc  = (const float*)d_in[6];
    const float* bc  = (const float*)d_in[7];
    const float* Wr  = (const float*)d_in[8];
    const float* br  = (const float*)d_in[9];
    float* out = (float*)d_out;

    cudaFuncSetAttribute(k_conv, cudaFuncAttributeMaxDynamicSharedMemorySize, SMEM_BYTES);
    k_prep<<<(CIN * 50 + 255) / 256, 256>>>(Wh);
    dim3 grid(B_, NGRP);
    k_conv<<<grid, 256, SMEM_BYTES>>>(F, pi, ni);
    k_reduce<<<(NENT * HID2 + 255) / 256, 256>>>();
    k_head<<<(NENT + 255) / 256, 256>>>(pi, ni, pa, bh, Wc, bc, Wr, br, out);
}